// round 1
// baseline (speedup 1.0000x reference)
#include <cuda_runtime.h>
#include <cstdint>

// path[row][t] = 0.3 + (lam0[row] - 0.3) * 0.5^t   (exact closed form of the scan;
// clamp is inactive after step 0 since 0.5*lam+0.15 in [0.15,0.65] for lam in [0,1],
// and t=0 emits lam0 itself: fmaf(diff, 1.0f, 0.3f) == lam0 to within 1 ulp).
//
// Layout: out is row-major [131072, 256]. Each thread writes one float4
// (4 consecutive t). 64 threads cover one row (1 KB), warps are 64-aligned
// so the lam0 load is warp-uniform (single broadcast request).

static constexpr int HORIZON = 256;
static constexpr int T4_PER_ROW = HORIZON / 4;   // 64 float4 per row

__global__ __launch_bounds__(256) void lyap_path_kernel(
    const float* __restrict__ lam0, float* __restrict__ out, unsigned n4)
{
    unsigned idx4 = blockIdx.x * 256u + threadIdx.x;
    if (idx4 >= n4) return;

    unsigned row = idx4 >> 6;                 // idx4 / T4_PER_ROW
    int t = (int)(idx4 & (T4_PER_ROW - 1)) << 2;  // first of 4 time steps

    float diff = __ldg(&lam0[row]) - 0.3f;

    // 0.5^t as exact power of two via exponent bits; t >= 127 underflows -> 0
    // (by then the path has converged to 0.3 to fp32 precision anyway).
    int e = 127 - t;
    float f0 = (e > 0) ? __uint_as_float((unsigned)e << 23) : 0.0f;
    float f1 = f0 * 0.5f;
    float f2 = f1 * 0.5f;
    float f3 = f2 * 0.5f;

    float4 v;
    v.x = fmaf(diff, f0, 0.3f);
    v.y = fmaf(diff, f1, 0.3f);
    v.z = fmaf(diff, f2, 0.3f);
    v.w = fmaf(diff, f3, 0.3f);

    reinterpret_cast<float4*>(out)[idx4] = v;
}

extern "C" void kernel_launch(void* const* d_in, const int* in_sizes, int n_in,
                              void* d_out, int out_size)
{
    const float* lam0 = (const float*)d_in[0];
    float* out = (float*)d_out;

    unsigned n4 = (unsigned)(out_size / 4);           // 8,388,608 float4
    unsigned grid = (n4 + 255u) / 256u;               // 32,768 blocks

    lyap_path_kernel<<<grid, 256>>>(lam0, out, n4);
}

// round 2
// speedup vs baseline: 1.2894x; 1.2894x over previous
#include <cuda_runtime.h>
#include <cstdint>

// path[row][t] = 0.3 + (lam0[row] - 0.3) * 0.5^t   (closed form of the scan;
// clamp inactive after step 0, 0.5^t exact power of two via exponent bits).
//
// R2: grid-stride persistent blocks. 2048 blocks x 256 threads; each thread
// writes 16 float4 (STG.128) across the grid-stride loop, unrolled x4 so 4
// independent stores are in flight per window. Eliminates ~30 wave
// transitions of the R1 launch (32768 blocks) and amortizes per-thread
// fixed cost over 256 B instead of 16 B.

static constexpr int HORIZON = 256;
static constexpr int T4_PER_ROW = HORIZON / 4;   // 64 float4 per row
static constexpr unsigned GRID = 2048;
static constexpr unsigned BLOCK = 256;

__global__ __launch_bounds__(BLOCK) void lyap_path_kernel(
    const float* __restrict__ lam0, float* __restrict__ out, unsigned n4)
{
    const unsigned stride = GRID * BLOCK;               // 524288
    unsigned idx4 = blockIdx.x * BLOCK + threadIdx.x;

    float4* __restrict__ out4 = reinterpret_cast<float4*>(out);

    #pragma unroll 4
    for (; idx4 < n4; idx4 += stride) {
        unsigned row = idx4 >> 6;                        // idx4 / T4_PER_ROW
        int t = (int)(idx4 & (T4_PER_ROW - 1)) << 2;     // first of 4 time steps

        float diff = __ldg(&lam0[row]) - 0.3f;

        // 0.5^t exactly; t >= 127 underflows to 0 (path converged to 0.3f long before).
        int e = 127 - t;
        float f0 = (e > 0) ? __uint_as_float((unsigned)e << 23) : 0.0f;
        float f1 = f0 * 0.5f;
        float f2 = f1 * 0.5f;
        float f3 = f2 * 0.5f;

        float4 v;
        v.x = fmaf(diff, f0, 0.3f);
        v.y = fmaf(diff, f1, 0.3f);
        v.z = fmaf(diff, f2, 0.3f);
        v.w = fmaf(diff, f3, 0.3f);

        out4[idx4] = v;
    }
}

extern "C" void kernel_launch(void* const* d_in, const int* in_sizes, int n_in,
                              void* d_out, int out_size)
{
    const float* lam0 = (const float*)d_in[0];
    float* out = (float*)d_out;

    unsigned n4 = (unsigned)(out_size / 4);              // 8,388,608 float4

    lyap_path_kernel<<<GRID, BLOCK>>>(lam0, out, n4);
}

// round 3
// speedup vs baseline: 1.3597x; 1.0545x over previous
#include <cuda_runtime.h>
#include <cstdint>

// path[row][t] = 0.3 + (lam0[row] - 0.3) * 0.5^t   (closed form of the scan;
// clamp inactive after step 0; 0.5^t exact power of two via exponent bits).
//
// R3: grid stride is a multiple of 64 (= float4s per row), so each thread's
// time-offset t -- and therefore the four 0.5^t factors -- is LOOP-INVARIANT.
// Hoisted out of the loop; body is just {broadcast LDG, 4 FMA, STG.128}.
// Streaming stores (__stcs, evict-first) since output is write-once.
// Grid 2368 = 148 SMs x 16 blocks, unroll 8 for store MLP.

static constexpr int HORIZON = 256;
static constexpr int T4_PER_ROW = HORIZON / 4;     // 64 float4 per row
static constexpr unsigned GRID = 2368;             // 148 * 16
static constexpr unsigned BLOCK = 256;
static constexpr unsigned STRIDE = GRID * BLOCK;   // 606208, multiple of 64

__global__ __launch_bounds__(BLOCK) void lyap_path_kernel(
    const float* __restrict__ lam0, float* __restrict__ out, unsigned n4)
{
    unsigned idx4 = blockIdx.x * BLOCK + threadIdx.x;
    if (idx4 >= n4) return;

    // Loop-invariant: t = 4 * (idx4 % 64) is fixed for this thread because
    // STRIDE % 64 == 0. Compute the four decay factors once.
    int t = (int)(idx4 & (T4_PER_ROW - 1)) << 2;
    int e = 127 - t;
    const float f0 = (e > 0) ? __uint_as_float((unsigned)e << 23) : 0.0f;
    const float f1 = f0 * 0.5f;
    const float f2 = f1 * 0.5f;
    const float f3 = f2 * 0.5f;

    float4* __restrict__ out4 = reinterpret_cast<float4*>(out);
    const unsigned row_stride = STRIDE / T4_PER_ROW;   // 9472

    unsigned row = idx4 >> 6;

    #pragma unroll 8
    for (; idx4 < n4; idx4 += STRIDE, row += row_stride) {
        float diff = __ldg(&lam0[row]) - 0.3f;

        float4 v;
        v.x = fmaf(diff, f0, 0.3f);
        v.y = fmaf(diff, f1, 0.3f);
        v.z = fmaf(diff, f2, 0.3f);
        v.w = fmaf(diff, f3, 0.3f);

        __stcs(&out4[idx4], v);   // streaming store: write-once, evict-first
    }
}

extern "C" void kernel_launch(void* const* d_in, const int* in_sizes, int n_in,
                              void* d_out, int out_size)
{
    const float* lam0 = (const float*)d_in[0];
    float* out = (float*)d_out;

    unsigned n4 = (unsigned)(out_size / 4);            // 8,388,608 float4

    lyap_path_kernel<<<GRID, BLOCK>>>(lam0, out, n4);
}